// round 15
// baseline (speedup 1.0000x reference)
#include <cuda_runtime.h>
#include <cuda_bf16.h>
#include <math.h>
#include <cstdint>

#if defined(__CUDA_ARCH__) && defined(__CUDA_ARCH_FEAT_SM103_ALL)
#define TC05 1
#else
#define TC05 0
#endif

#define Bsz 32
#define Lsz 512
#define Dm  288
#define D3  864
#define Hh  8
#define HD  36
#define Vv  4096
#define TOK (Bsz*Lsz)   // 16384
#define KP1 320
#define KP3 896
#define QKN 960         // qkv/rec_in padded N (5*192)
#define GUN 1920        // fused gate+up padded N (10*192), rows interleaved (g,u)
#define VP  4224        // logits padded N (22*192)

#define NCHS 32
#define CHL  16

// padded weight offsets (elements)
#define WQKV  0ull
#define WAOUT 1228800ull
#define WRIN  1597440ull
#define WROUT 4669440ull
#define WGU   5591040ull
#define WDOWN 14192640ull
#define WEMB  17805312ull
#define WTOT  19156992ull

// attention smem: sK[512][37] + sV[512][37] floats
#define ASMEM (2*512*37*4)

// ---------------- scratch (device globals; zero-initialized) ----------------
__device__ float g_h [TOK*Dm];
__device__ float g_a [TOK*D3];
__device__ float g_ca[Bsz*NCHS*Dm];
__device__ float g_ch[Bsz*NCHS*Dm];

__device__ __nv_bfloat16 g_wh [WTOT];
__device__ __nv_bfloat16 g_wl [WTOT];
__device__ __nv_bfloat16 g_xnh[TOK*KP1];
__device__ __nv_bfloat16 g_xnl[TOK*KP1];
__device__ __nv_bfloat16 g_ash[TOK*KP3];
__device__ __nv_bfloat16 g_asl[TOK*KP3];
__device__ __nv_bfloat16 g_th [TOK*KP1];
__device__ __nv_bfloat16 g_tl [TOK*KP1];

// ---------------- helpers ----------------------------------------------------
__device__ __forceinline__ void bf16split(float v, __nv_bfloat16* hi, __nv_bfloat16* lo)
{
    __nv_bfloat16 h = __float2bfloat16_rn(v);
    *hi = h;
    *lo = __float2bfloat16_rn(v - __bfloat162float(h));
}

#if TC05
__device__ __forceinline__ uint32_t elect1()
{
    uint32_t p;
    asm volatile("{\n\t.reg .pred p;\n\telect.sync _|p, 0xFFFFFFFF;\n\tselp.b32 %0,1,0,p;\n\t}" : "=r"(p));
    return p;
}

__device__ __forceinline__ void mbar_wait(uint32_t mbar, uint32_t parity)
{
    asm volatile(
        "{\n\t.reg .pred P1;\n\t"
        "WAIT_LOOP_%=:\n\t"
        "mbarrier.try_wait.parity.acquire.cta.shared::cta.b64 P1, [%0], %1, 0x989680;\n\t"
        "@P1 bra.uni WAIT_DONE_%=;\n\t"
        "bra.uni WAIT_LOOP_%=;\n\t"
        "WAIT_DONE_%=:\n\t}"
        :: "r"(mbar), "r"(parity) : "memory");
}

__device__ __forceinline__ uint64_t mk_desc(uint32_t smem_addr)
{
    const uint64_t base =
        (uint64_t(2)  << 61)
      | (uint64_t(1)  << 46)
      | (uint64_t(64) << 32)
      | (uint64_t(1)  << 16);
    return base | ((uint64_t)(smem_addr >> 4) & 0x3FFF);
}

__device__ __forceinline__ void mma_f16_ss(uint32_t d, uint64_t ad, uint64_t bd,
                                           uint32_t idesc, bool accum)
{
    uint32_t en = accum ? 1u : 0u;
    asm volatile(
        "{\n\t.reg .pred p;\n\t"
        "setp.ne.u32 p, %4, 0;\n\t"
        "tcgen05.mma.cta_group::1.kind::f16 [%0], %1, %2, %3, {%5, %5, %5, %5}, p;\n\t"
        "}"
        :: "r"(d), "l"(ad), "l"(bd), "r"(idesc), "r"(en), "r"(0u)
        : "memory");
}

#define LDTM32(r, addr) \
    asm volatile( \
        "tcgen05.ld.sync.aligned.32x32b.x32.b32 " \
        "{%0, %1, %2, %3, %4, %5, %6, %7, " \
        " %8, %9, %10, %11, %12, %13, %14, %15, " \
        " %16, %17, %18, %19, %20, %21, %22, %23, " \
        " %24, %25, %26, %27, %28, %29, %30, %31}, [%32];" \
        : "=r"((r)[0]),  "=r"((r)[1]),  "=r"((r)[2]),  "=r"((r)[3]), \
          "=r"((r)[4]),  "=r"((r)[5]),  "=r"((r)[6]),  "=r"((r)[7]), \
          "=r"((r)[8]),  "=r"((r)[9]),  "=r"((r)[10]), "=r"((r)[11]), \
          "=r"((r)[12]), "=r"((r)[13]), "=r"((r)[14]), "=r"((r)[15]), \
          "=r"((r)[16]), "=r"((r)[17]), "=r"((r)[18]), "=r"((r)[19]), \
          "=r"((r)[20]), "=r"((r)[21]), "=r"((r)[22]), "=r"((r)[23]), \
          "=r"((r)[24]), "=r"((r)[25]), "=r"((r)[26]), "=r"((r)[27]), \
          "=r"((r)[28]), "=r"((r)[29]), "=r"((r)[30]), "=r"((r)[31]) \
        : "r"(addr))
#endif  // TC05

// ---------------- weight split: 2 elems/thread, row map r -> r*rowmul+rowadd ---
__global__ void wsplit_k(const float* __restrict__ src, __nv_bfloat16* __restrict__ hi,
                         __nv_bfloat16* __restrict__ lo, int layers, int Nr, int Nb,
                         int K, int Kp, int rowmul, int rowadd)
{
    int e = (blockIdx.x*blockDim.x + threadIdx.x) * 2;
    if (e >= layers*Nr*K) return;
    int k = e % K;
    int r = (e / K) % Nr;
    int l = e / (K*Nr);
    float2 v = *(const float2*)(src + e);
    __nv_bfloat16 h0 = __float2bfloat16_rn(v.x);
    __nv_bfloat16 l0 = __float2bfloat16_rn(v.x - __bfloat162float(h0));
    __nv_bfloat16 h1 = __float2bfloat16_rn(v.y);
    __nv_bfloat16 l1 = __float2bfloat16_rn(v.y - __bfloat162float(h1));
    size_t dst = ((size_t)l*Nb + (size_t)r*rowmul + rowadd)*Kp + k;
    *(__nv_bfloat162*)(hi + dst) = __nv_bfloat162(h0, h1);
    *(__nv_bfloat162*)(lo + dst) = __nv_bfloat162(l0, l1);
}

// ---------------- embedding ---------------------------------------------------
__global__ void embed_k(const int* __restrict__ x, const float* __restrict__ emb,
                        const float* __restrict__ pos, float* __restrict__ h)
{
    int t = blockIdx.x;
    int d = threadIdx.x;
    int tok = x[t];
    int l = t & (Lsz-1);
    h[(size_t)t*Dm + d] = emb[(size_t)tok*Dm + d] + pos[(size_t)l*Dm + d];
}

// ---------------- rmsnorm (warp per token), vectorized -------------------------
__global__ void rmsnorm_k(const float* __restrict__ x, const float* __restrict__ scale,
                          __nv_bfloat16* __restrict__ yh, __nv_bfloat16* __restrict__ yl)
{
    int gw   = (blockIdx.x*blockDim.x + threadIdx.x) >> 5;
    int lane = threadIdx.x & 31;
    if (gw >= TOK) return;
    const float* xr = x + (size_t)gw*Dm;
    const float4* x4 = (const float4*)xr;
    float4 va = x4[lane];
    float4 vb = x4[lane + 32];
    float  vc = xr[256 + lane];
    float ss = va.x*va.x + va.y*va.y + va.z*va.z + va.w*va.w
             + vb.x*vb.x + vb.y*vb.y + vb.z*vb.z + vb.w*vb.w
             + vc*vc;
#pragma unroll
    for (int off = 16; off; off >>= 1) ss += __shfl_xor_sync(~0u, ss, off);
    float norm = sqrtf(ss * (1.f/Dm));
    float inv  = 1.f / (norm + 1e-6f);

    const float4* s4 = (const float4*)scale;
    float4 sa = s4[lane];
    float4 sb = s4[lane + 32];
    float  sc = scale[256 + lane];

    size_t base = (size_t)gw*KP1;
    float y[8] = { sa.x*va.x*inv, sa.y*va.y*inv, sa.z*va.z*inv, sa.w*va.w*inv,
                   sb.x*vb.x*inv, sb.y*vb.y*inv, sb.z*vb.z*inv, sb.w*vb.w*inv };
    __nv_bfloat16 hh[8], ll[8];
#pragma unroll
    for (int j = 0; j < 8; j++) {
        hh[j] = __float2bfloat16_rn(y[j]);
        ll[j] = __float2bfloat16_rn(y[j] - __bfloat162float(hh[j]));
    }
    *(__nv_bfloat162*)(yh + base + 4*lane)       = __nv_bfloat162(hh[0], hh[1]);
    *(__nv_bfloat162*)(yh + base + 4*lane + 2)   = __nv_bfloat162(hh[2], hh[3]);
    *(__nv_bfloat162*)(yh + base + 128 + 4*lane)     = __nv_bfloat162(hh[4], hh[5]);
    *(__nv_bfloat162*)(yh + base + 128 + 4*lane + 2) = __nv_bfloat162(hh[6], hh[7]);
    *(__nv_bfloat162*)(yl + base + 4*lane)       = __nv_bfloat162(ll[0], ll[1]);
    *(__nv_bfloat162*)(yl + base + 4*lane + 2)   = __nv_bfloat162(ll[2], ll[3]);
    *(__nv_bfloat162*)(yl + base + 128 + 4*lane)     = __nv_bfloat162(ll[4], ll[5]);
    *(__nv_bfloat162*)(yl + base + 128 + 4*lane + 2) = __nv_bfloat162(ll[6], ll[7]);
    float yc = sc*vc*inv;
    bf16split(yc, yh + base + 256 + lane, yl + base + 256 + lane);
}

// ---------------- tcgen05 bf16x3 GEMM, templated on BN (96: 2 CTA/SM; 192: 1) --
// mode 0: C = A*B^T; 1: +R; 2: silu-fused bf16 out; 3: rec sigmoid transform.
template <int BN>
__global__ void __launch_bounds__(256) gemm5_k(
    const __nv_bfloat16* __restrict__ Ah, const __nv_bfloat16* __restrict__ Al,
    const __nv_bfloat16* __restrict__ Bh, const __nv_bfloat16* __restrict__ Bl,
    const float* __restrict__ R, float* __restrict__ C,
    __nv_bfloat16* __restrict__ Oh, __nv_bfloat16* __restrict__ Ol,
    int Nreal, int K, int mode)
{
#if TC05
    constexpr int BPL   = BN*128;              // B plane bytes per stage
    constexpr int STGB  = 32768 + 2*BPL;       // stage bytes
    constexpr int BITER = BN/32;               // B load iterations
    constexpr uint32_t IDESC = 0x8000490u | ((BN/8) << 17);
    constexpr uint32_t TCOLS = (BN == 96) ? 128u : 256u;
    constexpr int PIT = BN + 1;

    extern __shared__ __align__(1024) char smraw[];
    __shared__ uint32_t s_tmem;
    __shared__ __align__(8) unsigned long long s_mbar[2];

    const int tid  = threadIdx.x;
    const int wid  = tid >> 5;
    const int lane = tid & 31;
    const int m0   = blockIdx.y * 128;
    const int n0   = blockIdx.x * BN;
    const int nch  = K >> 6;

    uint32_t smb = (uint32_t)__cvta_generic_to_shared(smraw);
    uint32_t mb0 = (uint32_t)__cvta_generic_to_shared(&s_mbar[0]);
    uint32_t mb1 = (uint32_t)__cvta_generic_to_shared(&s_mbar[1]);

    if (wid == 0) {
        asm volatile("tcgen05.alloc.cta_group::1.sync.aligned.shared::cta.b32 [%0], %1;"
            :: "r"((uint32_t)__cvta_generic_to_shared(&s_tmem)), "r"(TCOLS) : "memory");
        asm volatile("tcgen05.relinquish_alloc_permit.cta_group::1.sync.aligned;");
    }
    if (tid == 0) {
        asm volatile("mbarrier.init.shared.b64 [%0], %1;" :: "r"(mb0), "r"(1u) : "memory");
        asm volatile("mbarrier.init.shared.b64 [%0], %1;" :: "r"(mb1), "r"(1u) : "memory");
    }
    __syncthreads();
    const uint32_t tmem = s_tmem;

    const char* gA0 = (const char*)(Ah + (size_t)m0*K);
    const char* gA1 = (const char*)(Al + (size_t)m0*K);
    const char* gB0 = (const char*)(Bh + (size_t)n0*K);
    const char* gB1 = (const char*)(Bl + (size_t)n0*K);
    const size_t pitch = (size_t)K * 2;

    auto load_chunk = [&](int c) {
        int st = c & 1;
        char* sb = smraw + st*STGB;
#pragma unroll
        for (int i = 0; i < 4; i++) {
            int idx = i*256 + tid;
            int row = idx >> 3;
            int kq  = (idx & 7) << 4;
            int so  = row*128 + kq;  so ^= (so >> 3) & 0x70;
            size_t go = (size_t)row*pitch + c*128 + kq;
            unsigned int d0 = (unsigned int)__cvta_generic_to_shared(sb + so);
            asm volatile("cp.async.cg.shared.global [%0], [%1], 16;" :: "r"(d0), "l"(gA0 + go));
            unsigned int d1 = (unsigned int)__cvta_generic_to_shared(sb + 16384 + so);
            asm volatile("cp.async.cg.shared.global [%0], [%1], 16;" :: "r"(d1), "l"(gA1 + go));
        }
#pragma unroll
        for (int i = 0; i < BITER; i++) {
            int idx = i*256 + tid;
            int row = idx >> 3;
            int kq  = (idx & 7) << 4;
            int so  = row*128 + kq;  so ^= (so >> 3) & 0x70;
            size_t go = (size_t)row*pitch + c*128 + kq;
            unsigned int d2 = (unsigned int)__cvta_generic_to_shared(sb + 32768 + so);
            asm volatile("cp.async.cg.shared.global [%0], [%1], 16;" :: "r"(d2), "l"(gB0 + go));
            unsigned int d3 = (unsigned int)__cvta_generic_to_shared(sb + 32768 + BPL + so);
            asm volatile("cp.async.cg.shared.global [%0], [%1], 16;" :: "r"(d3), "l"(gB1 + go));
        }
        asm volatile("cp.async.commit_group;");
    };

    load_chunk(0);
    if (nch > 1) load_chunk(1);

    int ph0 = 0, ph1 = 0;

    for (int c = 0; c < nch; c++) {
        int st = c & 1;
        if (c + 1 < nch) asm volatile("cp.async.wait_group 1;" ::: "memory");
        else             asm volatile("cp.async.wait_group 0;" ::: "memory");
        asm volatile("fence.proxy.async.shared::cta;" ::: "memory");
        __syncthreads();

        if (wid == 0 && elect1()) {
            uint32_t b = smb + st*STGB;
            uint64_t dAh = mk_desc(b);
            uint64_t dAl = mk_desc(b + 16384);
            uint64_t dBh = mk_desc(b + 32768);
            uint64_t dBl = mk_desc(b + 32768 + BPL);
            uint64_t ads[3] = {dAh, dAh, dAl};
            uint64_t bds[3] = {dBh, dBl, dBh};
#pragma unroll
            for (int t = 0; t < 3; t++)
#pragma unroll
                for (int k = 0; k < 4; k++)
                    mma_f16_ss(tmem, ads[t] + 2*k, bds[t] + 2*k, IDESC,
                               !(c == 0 && t == 0 && k == 0));
            uint32_t mb = st ? mb1 : mb0;
            asm volatile("tcgen05.commit.cta_group::1.mbarrier::arrive::one.shared::cluster.b64 [%0];"
                         :: "r"(mb) : "memory");
        }

        if (c + 2 < nch) {
            if (st) { mbar_wait(mb1, ph1); ph1 ^= 1; }
            else    { mbar_wait(mb0, ph0); ph0 ^= 1; }
            load_chunk(c + 2);
        }
    }
    for (int c = (nch >= 2 ? nch - 2 : 0); c < nch; c++) {
        int st = c & 1;
        if (st) { mbar_wait(mb1, ph1); ph1 ^= 1; } else { mbar_wait(mb0, ph0); ph0 ^= 1; }
    }
    asm volatile("tcgen05.fence::after_thread_sync;" ::: "memory");
    __syncthreads();

    float* smf = (float*)smraw;
    if (wid < 4) {
        int row = wid*32 + lane;
#pragma unroll
        for (int cb = 0; cb < BN/32; cb++) {
            uint32_t r[32];
            LDTM32(r, tmem + cb*32);
            asm volatile("tcgen05.wait::ld.sync.aligned;" ::: "memory");
            float* srow = smf + row*PIT + cb*32;
#pragma unroll
            for (int q = 0; q < 32; q++) srow[q] = __uint_as_float(r[q]);
        }
    }
    asm volatile("tcgen05.fence::before_thread_sync;" ::: "memory");
    __syncthreads();

    if (mode == 2) {
        int p0 = n0 >> 1;
#pragma unroll
        for (int i = 0; i < BN/4; i++) {
            int idx = i*256 + tid;
            int row = idx / (BN/2);
            int j   = idx % (BN/2);
            int p = p0 + j;
            if (p < D3) {
                const float* s = smf + row*PIT + 2*j;
                float g = s[0], u = s[1];
                float v = (g / (1.f + __expf(-g))) * u;
                size_t o = (size_t)(m0 + row)*KP3 + p;
                bf16split(v, Oh + o, Ol + o);
            }
        }
    } else {
#pragma unroll
        for (int i = 0; i < BN/8; i++) {
            int idx = i*256 + tid;
            int row = idx / (BN/4);
            int c4  = (idx % (BN/4)) << 2;
            int n = n0 + c4;
            if (n < Nreal) {
                const float* s = smf + row*PIT + c4;
                float4 v = make_float4(s[0], s[1], s[2], s[3]);
                size_t off = (size_t)(m0 + row)*Nreal + n;
                if (mode == 1) {
                    float4 rr = *(const float4*)(R + off);
                    v.x += rr.x; v.y += rr.y; v.z += rr.z; v.w += rr.w;
                } else if (mode == 3) {
                    int region = n / Dm;   // float4 never crosses a 288 boundary
                    if (region == 0) {
                        v.x = 1.f/(1.f + __expf(-v.x)); v.y = 1.f/(1.f + __expf(-v.y));
                        v.z = 1.f/(1.f + __expf(-v.z)); v.w = 1.f/(1.f + __expf(-v.w));
                    } else if (region == 2) {
                        v.x = 1.f/(1.f + __expf(1.f - v.x)); v.y = 1.f/(1.f + __expf(1.f - v.y));
                        v.z = 1.f/(1.f + __expf(1.f - v.z)); v.w = 1.f/(1.f + __expf(1.f - v.w));
                    }
                }
                *(float4*)(C + off) = v;
            }
        }
    }

    __syncthreads();
    if (tid == 0) {
        asm volatile("mbarrier.inval.shared.b64 [%0];" :: "r"(mb0) : "memory");
        asm volatile("mbarrier.inval.shared.b64 [%0];" :: "r"(mb1) : "memory");
    }
    if (wid == 0)
        asm volatile("tcgen05.dealloc.cta_group::1.sync.aligned.b32 %0, %1;" :: "r"(tmem), "r"(TCOLS));
#endif  // TC05
}

#define GSMEM96  (2*(32768 + 2*96*128))    // 114688
#define GSMEM192 (2*(32768 + 2*192*128))   // 163840

// ---------------- attention: 64 q/CTA, all K/V staged once ---------------------
__global__ void __launch_bounds__(512) attn_k(
    const float* __restrict__ qkv,
    __nv_bfloat16* __restrict__ oh, __nv_bfloat16* __restrict__ ol)
{
    extern __shared__ float asm_[];
    float (*sK)[37] = (float(*)[37])asm_;
    float (*sV)[37] = (float(*)[37])(asm_ + 512*37);

    int tid  = threadIdx.x;
    int wid  = tid >> 5;
    int lane = tid & 31;
    int bh = blockIdx.x >> 3;
    int qg = blockIdx.x & 7;
    int b = bh >> 3, h = bh & 7;

    int rows = (qg + 1) * 64;
    const float* kvbase = qkv + (size_t)b*Lsz*D3 + Dm + h*HD;

    for (int idx = tid; idx < rows*HD; idx += 512) {
        int kk = idx / HD;
        int dd = idx % HD;
        const float* src = kvbase + (size_t)kk*D3 + dd;
        sK[kk][dd] = src[0];
        sV[kk][dd] = src[Dm];
    }
    __syncthreads();

#pragma unroll
    for (int t = 0; t < 4; t++) {
        int q = qg*64 + t*16 + wid;

        const float* qrow = qkv + (size_t)(b*Lsz + q)*D3 + h*HD;
        float qv[HD];
#pragma unroll
        for (int d = 0; d < HD; d++) qv[d] = qrow[d] * (1.f/6.f);

        float m = -1e30f, ssum = 0.f;
        float o[HD];
#pragma unroll
        for (int d = 0; d < HD; d++) o[d] = 0.f;

        int nkc = (q >> 7) + 1;
        for (int kc = 0; kc < nkc; kc++) {
            float s[4], p[4];
            float cm = -1e30f;
#pragma unroll
            for (int j = 0; j < 4; j++) {
                int kk = (kc << 7) + lane + 32*j;
                s[j] = -1e30f;
                if (kk <= q) {
                    float a = 0.f;
#pragma unroll
                    for (int d = 0; d < HD; d++) a += qv[d] * sK[kk][d];
                    s[j] = a;
                }
                cm = fmaxf(cm, s[j]);
            }
#pragma unroll
            for (int off = 16; off; off >>= 1) cm = fmaxf(cm, __shfl_xor_sync(~0u, cm, off));
            float nm = fmaxf(m, cm);
            float alpha = __expf(m - nm);
            float ps = 0.f;
#pragma unroll
            for (int j = 0; j < 4; j++) {
                int kk = (kc << 7) + lane + 32*j;
                p[j] = (kk <= q) ? __expf(s[j] - nm) : 0.f;
                ps += p[j];
            }
#pragma unroll
            for (int off = 16; off; off >>= 1) ps += __shfl_xor_sync(~0u, ps, off);
            ssum = ssum*alpha + ps;
#pragma unroll
            for (int d = 0; d < HD; d++) {
                float acc = o[d]*alpha;
#pragma unroll
                for (int j = 0; j < 4; j++) {
                    int kk = (kc << 7) + lane + 32*j;
                    acc += p[j]*sV[kk][d];
                }
                o[d] = acc;
            }
            m = nm;
        }
#pragma unroll
        for (int d = 0; d < HD; d++) {
#pragma unroll
            for (int off = 16; off; off >>= 1) o[d] += __shfl_xor_sync(~0u, o[d], off);
        }
        if (lane == 0) {
            float inv = 1.f/ssum;
            size_t base = (size_t)(b*Lsz + q)*KP1 + h*HD;
#pragma unroll
            for (int d = 0; d < HD; d++)
                bf16split(o[d]*inv, oh + base + d, ol + base + d);
        }
    }
}

// ---------------- parallel linear recurrence scan (3 passes, sigmoids hoisted) -
__global__ void scan1_k(const float* __restrict__ gvf,
                        float* __restrict__ ca, float* __restrict__ ch)
{
    int idx = blockIdx.x*blockDim.x + threadIdx.x;
    if (idx >= Bsz*NCHS*Dm) return;
    int d = idx % Dm;
    int c = (idx / Dm) % NCHS;
    int b = idx / (Dm*NCHS);
    const float* base = gvf + ((size_t)b*Lsz + c*CHL)*D3;
    float a = 1.f, h = 0.f;
    for (int l = 0; l < CHL; l++) {
        const float* r = base + (size_t)l*D3;
        float v = r[Dm + d], ft = r[2*Dm + d];
        h = ft*h + (1.f - ft)*v;
        a *= ft;
    }
    ca[idx] = a;
    ch[idx] = h;
}

__global__ void scan2_k(const float* __restrict__ ca, float* __restrict__ ch)
{
    int idx = blockIdx.x*blockDim.x + threadIdx.x;
    if (idx >= Bsz*Dm) return;
    int d = idx % Dm, b = idx / Dm;
    float h = 0.f;
#pragma unroll
    for (int c = 0; c < NCHS; c++) {
        size_t o = ((size_t)b*NCHS + c)*Dm + d;
        float a = ca[o], hl = ch[o];
        ch[o] = h;
        h = a*h + hl;
    }
}

__global__ void scan3_k(const float* __restrict__ gvf, const float* __restrict__ ch,
                        __nv_bfloat16* __restrict__ oh, __nv_bfloat16* __restrict__ ol)
{
    int idx = blockIdx.x*blockDim.x + threadIdx.x;
    if (idx >= Bsz*NCHS*Dm) return;
    int d = idx % Dm;
    int c = (idx / Dm) % NCHS;
    int b = idx / (Dm*NCHS);
    const float* base = gvf + ((size_t)b*Lsz + c*CHL)*D3;
    float h = ch[idx];
    for (int l = 0; l < CHL; l++) {
        const float* r = base + (size_t)l*D3;
        float gs = r[d], v = r[Dm + d], ft = r[2*Dm + d];
        h = ft*h + (1.f - ft)*v;
        size_t o = ((size_t)(b*Lsz + c*CHL + l))*KP1 + d;
        bf16split(gs*h, oh + o, ol + o);
    }
}

// ---------------- host orchestration -------------------------------------------
static inline void run_gemm(int BN,
                            const __nv_bfloat16* Ah, const __nv_bfloat16* Al,
                            const __nv_bfloat16* wh, const __nv_bfloat16* wl, size_t woff,
                            const float* R, float* C,
                            __nv_bfloat16* Oh, __nv_bfloat16* Ol,
                            int Nb, int Nreal, int Kp, int mode)
{
    dim3 grid(Nb/BN, TOK/128);
    if (BN == 96)
        gemm5_k<96><<<grid, 256, GSMEM96>>>(Ah, Al, wh + woff, wl + woff, R, C, Oh, Ol, Nreal, Kp, mode);
    else
        gemm5_k<192><<<grid, 256, GSMEM192>>>(Ah, Al, wh + woff, wl + woff, R, C, Oh, Ol, Nreal, Kp, mode);
}

extern "C" void kernel_launch(void* const* d_in, const int* in_sizes, int n_in,
                              void* d_out, int out_size)
{
    const int*   x         = (const int*)  d_in[0];
    const float* emb       = (const float*)d_in[1];
    const float* pos_emb   = (const float*)d_in[2];
    const float* attn_qkv  = (const float*)d_in[3];
    const float* attn_out  = (const float*)d_in[4];
    const float* attn_norm = (const float*)d_in[5];
    const float* rec_in    = (const float*)d_in[6];
    const float* rec_out   = (const float*)d_in[7];
    const float* rec_norm  = (const float*)d_in[8];
    const float* ffn_gate  = (const float*)d_in[9];
    const float* ffn_up    = (const float*)d_in[10];
    const float* ffn_down  = (const float*)d_in[11];
    const float* ffn_norm  = (const float*)d_in[12];
    const float* final_nrm = (const float*)d_in[13];
    float* out = (float*)d_out;

    static int smem_set = 0;
    if (!smem_set) {
        cudaFuncSetAttribute(gemm5_k<96>,  cudaFuncAttributeMaxDynamicSharedMemorySize, GSMEM96);
        cudaFuncSetAttribute(gemm5_k<192>, cudaFuncAttributeMaxDynamicSharedMemorySize, GSMEM192);
        cudaFuncSetAttribute(attn_k,       cudaFuncAttributeMaxDynamicSharedMemorySize, ASMEM);
        smem_set = 1;
    }

    float *ph, *pa, *pca, *pch;
    __nv_bfloat16 *pwh, *pwl, *pxnh, *pxnl, *pash, *pasl, *pth, *ptl;
    cudaGetSymbolAddress((void**)&ph,  g_h);
    cudaGetSymbolAddress((void**)&pa,  g_a);
    cudaGetSymbolAddress((void**)&pca, g_ca);
    cudaGetSymbolAddress((void**)&pch, g_ch);
    cudaGetSymbolAddress((void**)&pwh, g_wh);
    cudaGetSymbolAddress((void**)&pwl, g_wl);
    cudaGetSymbolAddress((void**)&pxnh, g_xnh);
    cudaGetSymbolAddress((void**)&pxnl, g_xnl);
    cudaGetSymbolAddress((void**)&pash, g_ash);
    cudaGetSymbolAddress((void**)&pasl, g_asl);
    cudaGetSymbolAddress((void**)&pth, g_th);
    cudaGetSymbolAddress((void**)&ptl, g_tl);

    struct { const float* src; size_t off; int layers, Nr, Nb, K, Kp, rowmul, rowadd; } ws[8] = {
        {attn_qkv, WQKV,   4, 864, QKN, 288, 320, 1, 0},
        {attn_out, WAOUT,  4, 288, 288, 288, 320, 1, 0},
        {rec_in,   WRIN,  10, 864, QKN, 288, 320, 1, 0},
        {rec_out,  WROUT, 10, 288, 288, 288, 320, 1, 0},
        {ffn_gate, WGU,   14, 864, GUN, 288, 320, 2, 0},
        {ffn_up,   WGU,   14, 864, GUN, 288, 320, 2, 1},
        {ffn_down, WDOWN, 14, 288, 288, 864, 896, 1, 0},
        {emb,      WEMB,   1, 4096, VP, 288, 320, 1, 0},
    };
    for (int i = 0; i < 8; i++) {
        int tot = ws[i].layers * ws[i].Nr * ws[i].K;
        wsplit_k<<<(tot/2 + 255)/256, 256>>>(ws[i].src, pwh + ws[i].off, pwl + ws[i].off,
                                             ws[i].layers, ws[i].Nr, ws[i].Nb, ws[i].K,
                                             ws[i].Kp, ws[i].rowmul, ws[i].rowadd);
    }

    const int rms_blocks  = (TOK*32 + 255)/256;
    const int sc13_blocks = (Bsz*NCHS*Dm + 255)/256;
    const int sc2_blocks  = (Bsz*Dm + 255)/256;

    embed_k<<<TOK, Dm>>>(x, emb, pos_emb, ph);

    int ai = 0, ri = 0;
    for (int i = 0; i < 14; i++) {
        bool is_attn = ((i + 1) % 3 == 0);
        if (is_attn) {
            rmsnorm_k<<<rms_blocks, 256>>>(ph, attn_norm + (size_t)ai*Dm, pxnh, pxnl);
            run_gemm(192, pxnh, pxnl, pwh, pwl, WQKV + (size_t)ai*QKN*320, nullptr, pa,
                     nullptr, nullptr, QKN, D3, 320, 0);
            attn_k<<<Bsz*Hh*8, 512, ASMEM>>>(pa, pth, ptl);
            run_gemm(96, pth, ptl, pwh, pwl, WAOUT + (size_t)ai*288*320, ph, ph,
                     nullptr, nullptr, 288, Dm, 320, 1);
            ai++;
        } else {
            rmsnorm_k<<<rms_blocks, 256>>>(ph, rec_norm + (size_t)ri*Dm, pxnh, pxnl);
            run_gemm(192, pxnh, pxnl, pwh, pwl, WRIN + (size_t)ri*QKN*320, nullptr, pa,
                     nullptr, nullptr, QKN, D3, 320, 3);
            scan1_k<<<sc13_blocks, 256>>>(pa, pca, pch);
            scan2_k<<<sc2_blocks, 256>>>(pca, pch);
            scan3_k<<<sc13_blocks, 256>>>(pa, pch, pth, ptl);
            run_gemm(96, pth, ptl, pwh, pwl, WROUT + (size_t)ri*288*320, ph, ph,
                     nullptr, nullptr, 288, Dm, 320, 1);
            ri++;
        }
        rmsnorm_k<<<rms_blocks, 256>>>(ph, ffn_norm + (size_t)i*Dm, pxnh, pxnl);
        run_gemm(192, pxnh, pxnl, pwh, pwl, WGU + (size_t)i*GUN*320, nullptr, nullptr,
                 pash, pasl, GUN, GUN, 320, 2);
        run_gemm(96, pash, pasl, pwh, pwl, WDOWN + (size_t)i*288*896, ph, ph,
                 nullptr, nullptr, 288, Dm, 896, 1);
    }

    rmsnorm_k<<<rms_blocks, 256>>>(ph, final_nrm, pxnh, pxnl);
    run_gemm(192, pxnh, pxnl, pwh, pwl, WEMB, nullptr, out, nullptr, nullptr, VP, Vv, 320, 0);
}

// round 16
// speedup vs baseline: 1.2244x; 1.2244x over previous
#include <cuda_runtime.h>
#include <cuda_bf16.h>
#include <math.h>
#include <cstdint>

#if defined(__CUDA_ARCH__) && defined(__CUDA_ARCH_FEAT_SM103_ALL)
#define TC05 1
#else
#define TC05 0
#endif

#define Bsz 32
#define Lsz 512
#define Dm  288
#define D3  864
#define Hh  8
#define HD  36
#define Vv  4096
#define TOK (Bsz*Lsz)   // 16384
#define KP1 320
#define KP3 896
#define GUN 1824        // fused gate+up padded N (19*96), rows interleaved (g,u)
#define VP  4128        // logits padded N (43*96)

#define NCHS 32
#define CHL  16

// padded weight offsets (elements)
#define WQKV  0ull
#define WAOUT 1105920ull
#define WRIN  1474560ull
#define WROUT 4239360ull
#define WGU   5160960ull
#define WDOWN 13332480ull
#define WEMB  16945152ull
#define WTOT  18266112ull

// attention smem: sK[512][37] + sV[512][37] floats
#define ASMEM (2*512*37*4)

// ---------------- scratch (device globals; zero-initialized) ----------------
__device__ float g_h [TOK*Dm];
__device__ float g_a [TOK*D3];
__device__ float g_ca[Bsz*NCHS*Dm];
__device__ float g_ch[Bsz*NCHS*Dm];

__device__ __nv_bfloat16 g_wh [WTOT];
__device__ __nv_bfloat16 g_wl [WTOT];
__device__ __nv_bfloat16 g_xnh[TOK*KP1];
__device__ __nv_bfloat16 g_xnl[TOK*KP1];
__device__ __nv_bfloat16 g_ash[TOK*KP3];
__device__ __nv_bfloat16 g_asl[TOK*KP3];
__device__ __nv_bfloat16 g_th [TOK*KP1];
__device__ __nv_bfloat16 g_tl [TOK*KP1];

// ---------------- helpers ----------------------------------------------------
__device__ __forceinline__ void bf16split(float v, __nv_bfloat16* hi, __nv_bfloat16* lo)
{
    __nv_bfloat16 h = __float2bfloat16_rn(v);
    *hi = h;
    *lo = __float2bfloat16_rn(v - __bfloat162float(h));
}

#if TC05
__device__ __forceinline__ uint32_t elect1()
{
    uint32_t p;
    asm volatile("{\n\t.reg .pred p;\n\telect.sync _|p, 0xFFFFFFFF;\n\tselp.b32 %0,1,0,p;\n\t}" : "=r"(p));
    return p;
}

__device__ __forceinline__ void mbar_wait(uint32_t mbar, uint32_t parity)
{
    asm volatile(
        "{\n\t.reg .pred P1;\n\t"
        "WAIT_LOOP_%=:\n\t"
        "mbarrier.try_wait.parity.acquire.cta.shared::cta.b64 P1, [%0], %1, 0x989680;\n\t"
        "@P1 bra.uni WAIT_DONE_%=;\n\t"
        "bra.uni WAIT_LOOP_%=;\n\t"
        "WAIT_DONE_%=:\n\t}"
        :: "r"(mbar), "r"(parity) : "memory");
}

__device__ __forceinline__ uint64_t mk_desc(uint32_t smem_addr)
{
    const uint64_t base =
        (uint64_t(2)  << 61)
      | (uint64_t(1)  << 46)
      | (uint64_t(64) << 32)
      | (uint64_t(1)  << 16);
    return base | ((uint64_t)(smem_addr >> 4) & 0x3FFF);
}

__device__ __forceinline__ void mma_f16_ss(uint32_t d, uint64_t ad, uint64_t bd,
                                           uint32_t idesc, bool accum)
{
    uint32_t en = accum ? 1u : 0u;
    asm volatile(
        "{\n\t.reg .pred p;\n\t"
        "setp.ne.u32 p, %4, 0;\n\t"
        "tcgen05.mma.cta_group::1.kind::f16 [%0], %1, %2, %3, {%5, %5, %5, %5}, p;\n\t"
        "}"
        :: "r"(d), "l"(ad), "l"(bd), "r"(idesc), "r"(en), "r"(0u)
        : "memory");
}

#define LDTM32(r, addr) \
    asm volatile( \
        "tcgen05.ld.sync.aligned.32x32b.x32.b32 " \
        "{%0, %1, %2, %3, %4, %5, %6, %7, " \
        " %8, %9, %10, %11, %12, %13, %14, %15, " \
        " %16, %17, %18, %19, %20, %21, %22, %23, " \
        " %24, %25, %26, %27, %28, %29, %30, %31}, [%32];" \
        : "=r"((r)[0]),  "=r"((r)[1]),  "=r"((r)[2]),  "=r"((r)[3]), \
          "=r"((r)[4]),  "=r"((r)[5]),  "=r"((r)[6]),  "=r"((r)[7]), \
          "=r"((r)[8]),  "=r"((r)[9]),  "=r"((r)[10]), "=r"((r)[11]), \
          "=r"((r)[12]), "=r"((r)[13]), "=r"((r)[14]), "=r"((r)[15]), \
          "=r"((r)[16]), "=r"((r)[17]), "=r"((r)[18]), "=r"((r)[19]), \
          "=r"((r)[20]), "=r"((r)[21]), "=r"((r)[22]), "=r"((r)[23]), \
          "=r"((r)[24]), "=r"((r)[25]), "=r"((r)[26]), "=r"((r)[27]), \
          "=r"((r)[28]), "=r"((r)[29]), "=r"((r)[30]), "=r"((r)[31]) \
        : "r"(addr))
#endif  // TC05

// ---------------- weight split: 2 elems/thread, row map r -> r*rowmul+rowadd ---
__global__ void wsplit_k(const float* __restrict__ src, __nv_bfloat16* __restrict__ hi,
                         __nv_bfloat16* __restrict__ lo, int layers, int Nr, int Nb,
                         int K, int Kp, int rowmul, int rowadd)
{
    int e = (blockIdx.x*blockDim.x + threadIdx.x) * 2;
    if (e >= layers*Nr*K) return;
    int k = e % K;
    int r = (e / K) % Nr;
    int l = e / (K*Nr);
    float2 v = *(const float2*)(src + e);
    __nv_bfloat16 h0 = __float2bfloat16_rn(v.x);
    __nv_bfloat16 l0 = __float2bfloat16_rn(v.x - __bfloat162float(h0));
    __nv_bfloat16 h1 = __float2bfloat16_rn(v.y);
    __nv_bfloat16 l1 = __float2bfloat16_rn(v.y - __bfloat162float(h1));
    size_t dst = ((size_t)l*Nb + (size_t)r*rowmul + rowadd)*Kp + k;
    *(__nv_bfloat162*)(hi + dst) = __nv_bfloat162(h0, h1);
    *(__nv_bfloat162*)(lo + dst) = __nv_bfloat162(l0, l1);
}

// ---------------- embedding ---------------------------------------------------
__global__ void embed_k(const int* __restrict__ x, const float* __restrict__ emb,
                        const float* __restrict__ pos, float* __restrict__ h)
{
    int t = blockIdx.x;
    int d = threadIdx.x;
    int tok = x[t];
    int l = t & (Lsz-1);
    h[(size_t)t*Dm + d] = emb[(size_t)tok*Dm + d] + pos[(size_t)l*Dm + d];
}

// ---------------- rmsnorm (warp per token), vectorized -------------------------
__global__ void rmsnorm_k(const float* __restrict__ x, const float* __restrict__ scale,
                          __nv_bfloat16* __restrict__ yh, __nv_bfloat16* __restrict__ yl)
{
    int gw   = (blockIdx.x*blockDim.x + threadIdx.x) >> 5;
    int lane = threadIdx.x & 31;
    if (gw >= TOK) return;
    const float* xr = x + (size_t)gw*Dm;
    const float4* x4 = (const float4*)xr;
    float4 va = x4[lane];
    float4 vb = x4[lane + 32];
    float  vc = xr[256 + lane];
    float ss = va.x*va.x + va.y*va.y + va.z*va.z + va.w*va.w
             + vb.x*vb.x + vb.y*vb.y + vb.z*vb.z + vb.w*vb.w
             + vc*vc;
#pragma unroll
    for (int off = 16; off; off >>= 1) ss += __shfl_xor_sync(~0u, ss, off);
    float norm = sqrtf(ss * (1.f/Dm));
    float inv  = 1.f / (norm + 1e-6f);

    const float4* s4 = (const float4*)scale;
    float4 sa = s4[lane];
    float4 sb = s4[lane + 32];
    float  sc = scale[256 + lane];

    size_t base = (size_t)gw*KP1;
    float y[8] = { sa.x*va.x*inv, sa.y*va.y*inv, sa.z*va.z*inv, sa.w*va.w*inv,
                   sb.x*vb.x*inv, sb.y*vb.y*inv, sb.z*vb.z*inv, sb.w*vb.w*inv };
    __nv_bfloat16 hh[8], ll[8];
#pragma unroll
    for (int j = 0; j < 8; j++) {
        hh[j] = __float2bfloat16_rn(y[j]);
        ll[j] = __float2bfloat16_rn(y[j] - __bfloat162float(hh[j]));
    }
    *(__nv_bfloat162*)(yh + base + 4*lane)       = __nv_bfloat162(hh[0], hh[1]);
    *(__nv_bfloat162*)(yh + base + 4*lane + 2)   = __nv_bfloat162(hh[2], hh[3]);
    *(__nv_bfloat162*)(yh + base + 128 + 4*lane)     = __nv_bfloat162(hh[4], hh[5]);
    *(__nv_bfloat162*)(yh + base + 128 + 4*lane + 2) = __nv_bfloat162(hh[6], hh[7]);
    *(__nv_bfloat162*)(yl + base + 4*lane)       = __nv_bfloat162(ll[0], ll[1]);
    *(__nv_bfloat162*)(yl + base + 4*lane + 2)   = __nv_bfloat162(ll[2], ll[3]);
    *(__nv_bfloat162*)(yl + base + 128 + 4*lane)     = __nv_bfloat162(ll[4], ll[5]);
    *(__nv_bfloat162*)(yl + base + 128 + 4*lane + 2) = __nv_bfloat162(ll[6], ll[7]);
    float yc = sc*vc*inv;
    bf16split(yc, yh + base + 256 + lane, yl + base + 256 + lane);
}

// ---------------- tcgen05 bf16x3 GEMM (M128 x N96 tile, 2 CTAs/SM) ------------
// mode 0: C = A*B^T; 1: +R; 2: silu-fused bf16 out; 3: rec sigmoid transform.
#define STG_B 57344
#define GSMEM (2*STG_B)

__global__ void __launch_bounds__(256) gemm5_k(
    const __nv_bfloat16* __restrict__ Ah, const __nv_bfloat16* __restrict__ Al,
    const __nv_bfloat16* __restrict__ Bh, const __nv_bfloat16* __restrict__ Bl,
    const float* __restrict__ R, float* __restrict__ C,
    __nv_bfloat16* __restrict__ Oh, __nv_bfloat16* __restrict__ Ol,
    int Nreal, int K, int mode)
{
#if TC05
    extern __shared__ __align__(1024) char smraw[];
    __shared__ uint32_t s_tmem;
    __shared__ __align__(8) unsigned long long s_mbar[2];

    const int tid  = threadIdx.x;
    const int wid  = tid >> 5;
    const int lane = tid & 31;
    const int m0   = blockIdx.y * 128;
    const int n0   = blockIdx.x * 96;
    const int nch  = K >> 6;

    uint32_t smb = (uint32_t)__cvta_generic_to_shared(smraw);
    uint32_t mb0 = (uint32_t)__cvta_generic_to_shared(&s_mbar[0]);
    uint32_t mb1 = (uint32_t)__cvta_generic_to_shared(&s_mbar[1]);

    if (wid == 0) {
        asm volatile("tcgen05.alloc.cta_group::1.sync.aligned.shared::cta.b32 [%0], %1;"
            :: "r"((uint32_t)__cvta_generic_to_shared(&s_tmem)), "r"(128u) : "memory");
        asm volatile("tcgen05.relinquish_alloc_permit.cta_group::1.sync.aligned;");
    }
    if (tid == 0) {
        asm volatile("mbarrier.init.shared.b64 [%0], %1;" :: "r"(mb0), "r"(1u) : "memory");
        asm volatile("mbarrier.init.shared.b64 [%0], %1;" :: "r"(mb1), "r"(1u) : "memory");
    }
    __syncthreads();
    const uint32_t tmem = s_tmem;

    const char* gA0 = (const char*)(Ah + (size_t)m0*K);
    const char* gA1 = (const char*)(Al + (size_t)m0*K);
    const char* gB0 = (const char*)(Bh + (size_t)n0*K);
    const char* gB1 = (const char*)(Bl + (size_t)n0*K);
    const size_t pitch = (size_t)K * 2;

#define LOAD_CHUNK(c)                                                             \
    do {                                                                          \
        int st_ = (c) & 1;                                                        \
        char* sb_ = smraw + st_*STG_B;                                            \
        _Pragma("unroll")                                                         \
        for (int i_ = 0; i_ < 4; i_++) {                                          \
            int idx_ = i_*256 + tid;                                              \
            int row_ = idx_ >> 3;                                                 \
            int kq_  = (idx_ & 7) << 4;                                           \
            int so_  = row_*128 + kq_;  so_ ^= (so_ >> 3) & 0x70;                 \
            size_t go_ = (size_t)row_*pitch + (c)*128 + kq_;                      \
            unsigned int d0_ = (unsigned int)__cvta_generic_to_shared(sb_ + so_); \
            asm volatile("cp.async.cg.shared.global [%0], [%1], 16;"              \
                         :: "r"(d0_), "l"(gA0 + go_));                            \
            unsigned int d1_ = (unsigned int)__cvta_generic_to_shared(sb_ + 16384 + so_); \
            asm volatile("cp.async.cg.shared.global [%0], [%1], 16;"              \
                         :: "r"(d1_), "l"(gA1 + go_));                            \
        }                                                                         \
        _Pragma("unroll")                                                         \
        for (int i_ = 0; i_ < 3; i_++) {                                          \
            int idx_ = i_*256 + tid;                                              \
            int row_ = idx_ >> 3;                                                 \
            int kq_  = (idx_ & 7) << 4;                                           \
            int so_  = row_*128 + kq_;  so_ ^= (so_ >> 3) & 0x70;                 \
            size_t go_ = (size_t)row_*pitch + (c)*128 + kq_;                      \
            unsigned int d2_ = (unsigned int)__cvta_generic_to_shared(sb_ + 32768 + so_); \
            asm volatile("cp.async.cg.shared.global [%0], [%1], 16;"              \
                         :: "r"(d2_), "l"(gB0 + go_));                            \
            unsigned int d3_ = (unsigned int)__cvta_generic_to_shared(sb_ + 45056 + so_); \
            asm volatile("cp.async.cg.shared.global [%0], [%1], 16;"              \
                         :: "r"(d3_), "l"(gB1 + go_));                            \
        }                                                                         \
        asm volatile("cp.async.commit_group;");                                   \
    } while (0)

    LOAD_CHUNK(0);
    if (nch > 1) LOAD_CHUNK(1);

    int ph0 = 0, ph1 = 0;
    const uint32_t idesc = 0x8180490u;   // F32 acc, BF16xBF16, N=96, M=128

    for (int c = 0; c < nch; c++) {
        int st = c & 1;
        if (c + 1 < nch) asm volatile("cp.async.wait_group 1;" ::: "memory");
        else             asm volatile("cp.async.wait_group 0;" ::: "memory");
        asm volatile("fence.proxy.async.shared::cta;" ::: "memory");
        __syncthreads();

        if (wid == 0 && elect1()) {
            uint32_t b = smb + st*STG_B;
            uint64_t dAh = mk_desc(b);
            uint64_t dAl = mk_desc(b + 16384);
            uint64_t dBh = mk_desc(b + 32768);
            uint64_t dBl = mk_desc(b + 45056);
            uint64_t ads[3] = {dAh, dAh, dAl};
            uint64_t bds[3] = {dBh, dBl, dBh};
#pragma unroll
            for (int t = 0; t < 3; t++)
#pragma unroll
                for (int k = 0; k < 4; k++)
                    mma_f16_ss(tmem, ads[t] + 2*k, bds[t] + 2*k, idesc,
                               !(c == 0 && t == 0 && k == 0));
            uint32_t mb = st ? mb1 : mb0;
            asm volatile("tcgen05.commit.cta_group::1.mbarrier::arrive::one.shared::cluster.b64 [%0];"
                         :: "r"(mb) : "memory");
        }

        if (c + 2 < nch) {
            if (st) { mbar_wait(mb1, ph1); ph1 ^= 1; }
            else    { mbar_wait(mb0, ph0); ph0 ^= 1; }
            LOAD_CHUNK(c + 2);
        }
    }
    for (int c = (nch >= 2 ? nch - 2 : 0); c < nch; c++) {
        int st = c & 1;
        if (st) { mbar_wait(mb1, ph1); ph1 ^= 1; } else { mbar_wait(mb0, ph0); ph0 ^= 1; }
    }
    asm volatile("tcgen05.fence::after_thread_sync;" ::: "memory");
    __syncthreads();

    float* smf = (float*)smraw;
    if (wid < 4) {
        int row = wid*32 + lane;
#pragma unroll
        for (int cb = 0; cb < 3; cb++) {
            uint32_t r[32];
            LDTM32(r, tmem + cb*32);
            asm volatile("tcgen05.wait::ld.sync.aligned;" ::: "memory");
            float* srow = smf + row*97 + cb*32;
#pragma unroll
            for (int q = 0; q < 32; q++) srow[q] = __uint_as_float(r[q]);
        }
    }
    asm volatile("tcgen05.fence::before_thread_sync;" ::: "memory");
    __syncthreads();

    if (mode == 2) {
        int p0 = n0 >> 1;
#pragma unroll
        for (int i = 0; i < 24; i++) {
            int idx = i*256 + tid;
            int row = idx / 48;
            int j   = idx % 48;
            int p = p0 + j;
            if (p < D3) {
                const float* s = smf + row*97 + 2*j;
                float g = s[0], u = s[1];
                float v = (g / (1.f + __expf(-g))) * u;
                size_t o = (size_t)(m0 + row)*KP3 + p;
                bf16split(v, Oh + o, Ol + o);
            }
        }
    } else {
        int region = (mode == 3) ? ((n0 < Dm) ? 0 : (n0 < 2*Dm) ? 1 : 2) : 1;
#pragma unroll
        for (int i = 0; i < 12; i++) {
            int idx = i*256 + tid;
            int row = idx / 24;
            int c4  = (idx % 24) << 2;
            int n = n0 + c4;
            if (n < Nreal) {
                const float* s = smf + row*97 + c4;
                float4 v = make_float4(s[0], s[1], s[2], s[3]);
                size_t off = (size_t)(m0 + row)*Nreal + n;
                if (mode == 1) {
                    float4 rr = *(const float4*)(R + off);
                    v.x += rr.x; v.y += rr.y; v.z += rr.z; v.w += rr.w;
                } else if (mode == 3) {
                    if (region == 0) {
                        v.x = 1.f/(1.f + __expf(-v.x)); v.y = 1.f/(1.f + __expf(-v.y));
                        v.z = 1.f/(1.f + __expf(-v.z)); v.w = 1.f/(1.f + __expf(-v.w));
                    } else if (region == 2) {
                        v.x = 1.f/(1.f + __expf(1.f - v.x)); v.y = 1.f/(1.f + __expf(1.f - v.y));
                        v.z = 1.f/(1.f + __expf(1.f - v.z)); v.w = 1.f/(1.f + __expf(1.f - v.w));
                    }
                }
                *(float4*)(C + off) = v;
            }
        }
    }

    __syncthreads();
    if (tid == 0) {
        asm volatile("mbarrier.inval.shared.b64 [%0];" :: "r"(mb0) : "memory");
        asm volatile("mbarrier.inval.shared.b64 [%0];" :: "r"(mb1) : "memory");
    }
    if (wid == 0)
        asm volatile("tcgen05.dealloc.cta_group::1.sync.aligned.b32 %0, %1;" :: "r"(tmem), "r"(128u));
#undef LOAD_CHUNK
#endif  // TC05
}

// ---------------- attention: 64 q/CTA, all K/V staged once (float4 loads) ------
__global__ void __launch_bounds__(512) attn_k(
    const float* __restrict__ qkv,
    __nv_bfloat16* __restrict__ oh, __nv_bfloat16* __restrict__ ol)
{
    extern __shared__ float asm_[];
    float (*sK)[37] = (float(*)[37])asm_;
    float (*sV)[37] = (float(*)[37])(asm_ + 512*37);

    int tid  = threadIdx.x;
    int wid  = tid >> 5;
    int lane = tid & 31;
    int bh = blockIdx.x >> 3;
    int qg = blockIdx.x & 7;
    int b = bh >> 3, h = bh & 7;

    int rows = (qg + 1) * 64;
    const float* kvbase = qkv + (size_t)b*Lsz*D3 + Dm + h*HD;

    // float4 staging: 9 float4 per row (HD=36), row starts 16B-aligned
    for (int idx = tid; idx < rows*9; idx += 512) {
        int kk = idx / 9;
        int j4 = idx % 9;
        const float* src = kvbase + (size_t)kk*D3 + j4*4;
        float4 kv = *(const float4*)src;
        float4 vv = *(const float4*)(src + Dm);
        float* kd = &sK[kk][j4*4];
        kd[0] = kv.x; kd[1] = kv.y; kd[2] = kv.z; kd[3] = kv.w;
        float* vd = &sV[kk][j4*4];
        vd[0] = vv.x; vd[1] = vv.y; vd[2] = vv.z; vd[3] = vv.w;
    }
    __syncthreads();

#pragma unroll
    for (int t = 0; t < 4; t++) {
        int q = qg*64 + t*16 + wid;

        const float* qrow = qkv + (size_t)(b*Lsz + q)*D3 + h*HD;
        float qv[HD];
#pragma unroll
        for (int d = 0; d < HD; d++) qv[d] = qrow[d] * (1.f/6.f);

        float m = -1e30f, ssum = 0.f;
        float o[HD];
#pragma unroll
        for (int d = 0; d < HD; d++) o[d] = 0.f;

        int nkc = (q >> 7) + 1;
        for (int kc = 0; kc < nkc; kc++) {
            float s[4], p[4];
            float cm = -1e30f;
#pragma unroll
            for (int j = 0; j < 4; j++) {
                int kk = (kc << 7) + lane + 32*j;
                s[j] = -1e30f;
                if (kk <= q) {
                    float a = 0.f;
#pragma unroll
                    for (int d = 0; d < HD; d++) a += qv[d] * sK[kk][d];
                    s[j] = a;
                }
                cm = fmaxf(cm, s[j]);
            }
#pragma unroll
            for (int off = 16; off; off >>= 1) cm = fmaxf(cm, __shfl_xor_sync(~0u, cm, off));
            float nm = fmaxf(m, cm);
            float alpha = __expf(m - nm);
            float ps = 0.f;
#pragma unroll
            for (int j = 0; j < 4; j++) {
                int kk = (kc << 7) + lane + 32*j;
                p[j] = (kk <= q) ? __expf(s[j] - nm) : 0.f;
                ps += p[j];
            }
#pragma unroll
            for (int off = 16; off; off >>= 1) ps += __shfl_xor_sync(~0u, ps, off);
            ssum = ssum*alpha + ps;
#pragma unroll
            for (int d = 0; d < HD; d++) {
                float acc = o[d]*alpha;
#pragma unroll
                for (int j = 0; j < 4; j++) {
                    int kk = (kc << 7) + lane + 32*j;
                    acc += p[j]*sV[kk][d];
                }
                o[d] = acc;
            }
            m = nm;
        }
#pragma unroll
        for (int d = 0; d < HD; d++) {
#pragma unroll
            for (int off = 16; off; off >>= 1) o[d] += __shfl_xor_sync(~0u, o[d], off);
        }
        if (lane == 0) {
            float inv = 1.f/ssum;
            size_t base = (size_t)(b*Lsz + q)*KP1 + h*HD;
#pragma unroll
            for (int d = 0; d < HD; d++)
                bf16split(o[d]*inv, oh + base + d, ol + base + d);
        }
    }
}

// ---------------- parallel linear recurrence scan (3 passes, sigmoids hoisted) -
__global__ void scan1_k(const float* __restrict__ gvf,
                        float* __restrict__ ca, float* __restrict__ ch)
{
    int idx = blockIdx.x*blockDim.x + threadIdx.x;
    if (idx >= Bsz*NCHS*Dm) return;
    int d = idx % Dm;
    int c = (idx / Dm) % NCHS;
    int b = idx / (Dm*NCHS);
    const float* base = gvf + ((size_t)b*Lsz + c*CHL)*D3;
    float a = 1.f, h = 0.f;
    for (int l = 0; l < CHL; l++) {
        const float* r = base + (size_t)l*D3;
        float v = r[Dm + d], ft = r[2*Dm + d];
        h = ft*h + (1.f - ft)*v;
        a *= ft;
    }
    ca[idx] = a;
    ch[idx] = h;
}

__global__ void scan2_k(const float* __restrict__ ca, float* __restrict__ ch)
{
    int idx = blockIdx.x*blockDim.x + threadIdx.x;
    if (idx >= Bsz*Dm) return;
    int d = idx % Dm, b = idx / Dm;
    float h = 0.f;
#pragma unroll
    for (int c = 0; c < NCHS; c++) {
        size_t o = ((size_t)b*NCHS + c)*Dm + d;
        float a = ca[o], hl = ch[o];
        ch[o] = h;
        h = a*h + hl;
    }
}

__global__ void scan3_k(const float* __restrict__ gvf, const float* __restrict__ ch,
                        __nv_bfloat16* __restrict__ oh, __nv_bfloat16* __restrict__ ol)
{
    int idx = blockIdx.x*blockDim.x + threadIdx.x;
    if (idx >= Bsz*NCHS*Dm) return;
    int d = idx % Dm;
    int c = (idx / Dm) % NCHS;
    int b = idx / (Dm*NCHS);
    const float* base = gvf + ((size_t)b*Lsz + c*CHL)*D3;
    float h = ch[idx];
    for (int l = 0; l < CHL; l++) {
        const float* r = base + (size_t)l*D3;
        float gs = r[d], v = r[Dm + d], ft = r[2*Dm + d];
        h = ft*h + (1.f - ft)*v;
        size_t o = ((size_t)(b*Lsz + c*CHL + l))*KP1 + d;
        bf16split(gs*h, oh + o, ol + o);
    }
}

// ---------------- host orchestration -------------------------------------------
static inline void run_gemm(const __nv_bfloat16* Ah, const __nv_bfloat16* Al,
                            const __nv_bfloat16* wh, const __nv_bfloat16* wl, size_t woff,
                            const float* R, float* C,
                            __nv_bfloat16* Oh, __nv_bfloat16* Ol,
                            int Nb, int Nreal, int Kp, int mode)
{
    dim3 grid(Nb/96, TOK/128);
    gemm5_k<<<grid, 256, GSMEM>>>(Ah, Al, wh + woff, wl + woff, R, C, Oh, Ol, Nreal, Kp, mode);
}

extern "C" void kernel_launch(void* const* d_in, const int* in_sizes, int n_in,
                              void* d_out, int out_size)
{
    const int*   x         = (const int*)  d_in[0];
    const float* emb       = (const float*)d_in[1];
    const float* pos_emb   = (const float*)d_in[2];
    const float* attn_qkv  = (const float*)d_in[3];
    const float* attn_out  = (const float*)d_in[4];
    const float* attn_norm = (const float*)d_in[5];
    const float* rec_in    = (const float*)d_in[6];
    const float* rec_out   = (const float*)d_in[7];
    const float* rec_norm  = (const float*)d_in[8];
    const float* ffn_gate  = (const float*)d_in[9];
    const float* ffn_up    = (const float*)d_in[10];
    const float* ffn_down  = (const float*)d_in[11];
    const float* ffn_norm  = (const float*)d_in[12];
    const float* final_nrm = (const float*)d_in[13];
    float* out = (float*)d_out;

    static int smem_set = 0;
    if (!smem_set) {
        cudaFuncSetAttribute(gemm5_k, cudaFuncAttributeMaxDynamicSharedMemorySize, GSMEM);
        cudaFuncSetAttribute(attn_k,  cudaFuncAttributeMaxDynamicSharedMemorySize, ASMEM);
        smem_set = 1;
    }

    float *ph, *pa, *pca, *pch;
    __nv_bfloat16 *pwh, *pwl, *pxnh, *pxnl, *pash, *pasl, *pth, *ptl;
    cudaGetSymbolAddress((void**)&ph,  g_h);
    cudaGetSymbolAddress((void**)&pa,  g_a);
    cudaGetSymbolAddress((void**)&pca, g_ca);
    cudaGetSymbolAddress((void**)&pch, g_ch);
    cudaGetSymbolAddress((void**)&pwh, g_wh);
    cudaGetSymbolAddress((void**)&pwl, g_wl);
    cudaGetSymbolAddress((void**)&pxnh, g_xnh);
    cudaGetSymbolAddress((void**)&pxnl, g_xnl);
    cudaGetSymbolAddress((void**)&pash, g_ash);
    cudaGetSymbolAddress((void**)&pasl, g_asl);
    cudaGetSymbolAddress((void**)&pth, g_th);
    cudaGetSymbolAddress((void**)&ptl, g_tl);

    struct { const float* src; size_t off; int layers, Nr, Nb, K, Kp, rowmul, rowadd; } ws[8] = {
        {attn_qkv, WQKV,   4, 864, 864, 288, 320, 1, 0},
        {attn_out, WAOUT,  4, 288, 288, 288, 320, 1, 0},
        {rec_in,   WRIN,  10, 864, 864, 288, 320, 1, 0},
        {rec_out,  WROUT, 10, 288, 288, 288, 320, 1, 0},
        {ffn_gate, WGU,   14, 864, GUN, 288, 320, 2, 0},
        {ffn_up,   WGU,   14, 864, GUN, 288, 320, 2, 1},
        {ffn_down, WDOWN, 14, 288, 288, 864, 896, 1, 0},
        {emb,      WEMB,   1, 4096, VP, 288, 320, 1, 0},
    };
    for (int i = 0; i < 8; i++) {
        int tot = ws[i].layers * ws[i].Nr * ws[i].K;
        wsplit_k<<<(tot/2 + 255)/256, 256>>>(ws[i].src, pwh + ws[i].off, pwl + ws[i].off,
                                             ws[i].layers, ws[i].Nr, ws[i].Nb, ws[i].K,
                                             ws[i].Kp, ws[i].rowmul, ws[i].rowadd);
    }

    const int rms_blocks  = (TOK*32 + 255)/256;
    const int sc13_blocks = (Bsz*NCHS*Dm + 255)/256;
    const int sc2_blocks  = (Bsz*Dm + 255)/256;

    embed_k<<<TOK, Dm>>>(x, emb, pos_emb, ph);

    int ai = 0, ri = 0;
    for (int i = 0; i < 14; i++) {
        bool is_attn = ((i + 1) % 3 == 0);
        if (is_attn) {
            rmsnorm_k<<<rms_blocks, 256>>>(ph, attn_norm + (size_t)ai*Dm, pxnh, pxnl);
            run_gemm(pxnh, pxnl, pwh, pwl, WQKV + (size_t)ai*864*320, nullptr, pa,
                     nullptr, nullptr, 864, D3, 320, 0);
            attn_k<<<Bsz*Hh*8, 512, ASMEM>>>(pa, pth, ptl);
            run_gemm(pth, ptl, pwh, pwl, WAOUT + (size_t)ai*288*320, ph, ph,
                     nullptr, nullptr, 288, Dm, 320, 1);
            ai++;
        } else {
            rmsnorm_k<<<rms_blocks, 256>>>(ph, rec_norm + (size_t)ri*Dm, pxnh, pxnl);
            run_gemm(pxnh, pxnl, pwh, pwl, WRIN + (size_t)ri*864*320, nullptr, pa,
                     nullptr, nullptr, 864, D3, 320, 3);
            scan1_k<<<sc13_blocks, 256>>>(pa, pca, pch);
            scan2_k<<<sc2_blocks, 256>>>(pca, pch);
            scan3_k<<<sc13_blocks, 256>>>(pa, pch, pth, ptl);
            run_gemm(pth, ptl, pwh, pwl, WROUT + (size_t)ri*288*320, ph, ph,
                     nullptr, nullptr, 288, Dm, 320, 1);
            ri++;
        }
        rmsnorm_k<<<rms_blocks, 256>>>(ph, ffn_norm + (size_t)i*Dm, pxnh, pxnl);
        run_gemm(pxnh, pxnl, pwh, pwl, WGU + (size_t)i*GUN*320, nullptr, nullptr,
                 pash, pasl, GUN, GUN, 320, 2);
        run_gemm(pash, pasl, pwh, pwl, WDOWN + (size_t)i*288*896, ph, ph,
                 nullptr, nullptr, 288, Dm, 896, 1);
    }

    rmsnorm_k<<<rms_blocks, 256>>>(ph, final_nrm, pxnh, pxnl);
    run_gemm(pxnh, pxnl, pwh, pwl, WEMB, nullptr, out, nullptr, nullptr, VP, Vv, 320, 0);
}

// round 17
// speedup vs baseline: 1.2272x; 1.0023x over previous
#include <cuda_runtime.h>
#include <cuda_bf16.h>
#include <math.h>
#include <cstdint>

#if defined(__CUDA_ARCH__) && defined(__CUDA_ARCH_FEAT_SM103_ALL)
#define TC05 1
#else
#define TC05 0
#endif

#define Bsz 32
#define Lsz 512
#define Dm  288
#define D3  864
#define Hh  8
#define HD  36
#define Vv  4096
#define TOK (Bsz*Lsz)   // 16384
#define KP1 320
#define KP3 896
#define GUN 1824        // fused gate+up padded N (19*96), rows interleaved (g,u)
#define VP  4128        // logits padded N (43*96)

#define NCHS 32
#define CHL  16

// padded weight offsets (elements)
#define WQKV  0ull
#define WAOUT 1105920ull
#define WRIN  1474560ull
#define WROUT 4239360ull
#define WGU   5160960ull
#define WDOWN 13332480ull
#define WEMB  16945152ull
#define WTOT  18266112ull

// attention smem: sK[512][37] + sV[512][37] floats
#define ASMEM (2*512*37*4)

// ---------------- scratch (device globals; zero-initialized) ----------------
__device__ float g_h [TOK*Dm];
__device__ float g_a [TOK*D3];
__device__ float g_ca[Bsz*NCHS*Dm];
__device__ float g_ch[Bsz*NCHS*Dm];

__device__ __nv_bfloat16 g_wh [WTOT];
__device__ __nv_bfloat16 g_wl [WTOT];
__device__ __nv_bfloat16 g_xnh[TOK*KP1];
__device__ __nv_bfloat16 g_xnl[TOK*KP1];
__device__ __nv_bfloat16 g_ash[TOK*KP3];
__device__ __nv_bfloat16 g_asl[TOK*KP3];
__device__ __nv_bfloat16 g_th [TOK*KP1];
__device__ __nv_bfloat16 g_tl [TOK*KP1];

// ---------------- helpers ----------------------------------------------------
__device__ __forceinline__ void bf16split(float v, __nv_bfloat16* hi, __nv_bfloat16* lo)
{
    __nv_bfloat16 h = __float2bfloat16_rn(v);
    *hi = h;
    *lo = __float2bfloat16_rn(v - __bfloat162float(h));
}

#if TC05
__device__ __forceinline__ uint32_t elect1()
{
    uint32_t p;
    asm volatile("{\n\t.reg .pred p;\n\telect.sync _|p, 0xFFFFFFFF;\n\tselp.b32 %0,1,0,p;\n\t}" : "=r"(p));
    return p;
}

__device__ __forceinline__ void mbar_wait(uint32_t mbar, uint32_t parity)
{
    asm volatile(
        "{\n\t.reg .pred P1;\n\t"
        "WAIT_LOOP_%=:\n\t"
        "mbarrier.try_wait.parity.acquire.cta.shared::cta.b64 P1, [%0], %1, 0x989680;\n\t"
        "@P1 bra.uni WAIT_DONE_%=;\n\t"
        "bra.uni WAIT_LOOP_%=;\n\t"
        "WAIT_DONE_%=:\n\t}"
        :: "r"(mbar), "r"(parity) : "memory");
}

__device__ __forceinline__ uint64_t mk_desc(uint32_t smem_addr)
{
    const uint64_t base =
        (uint64_t(2)  << 61)
      | (uint64_t(1)  << 46)
      | (uint64_t(64) << 32)
      | (uint64_t(1)  << 16);
    return base | ((uint64_t)(smem_addr >> 4) & 0x3FFF);
}

__device__ __forceinline__ void mma_f16_ss(uint32_t d, uint64_t ad, uint64_t bd,
                                           uint32_t idesc, bool accum)
{
    uint32_t en = accum ? 1u : 0u;
    asm volatile(
        "{\n\t.reg .pred p;\n\t"
        "setp.ne.u32 p, %4, 0;\n\t"
        "tcgen05.mma.cta_group::1.kind::f16 [%0], %1, %2, %3, {%5, %5, %5, %5}, p;\n\t"
        "}"
        :: "r"(d), "l"(ad), "l"(bd), "r"(idesc), "r"(en), "r"(0u)
        : "memory");
}

#define LDTM32(r, addr) \
    asm volatile( \
        "tcgen05.ld.sync.aligned.32x32b.x32.b32 " \
        "{%0, %1, %2, %3, %4, %5, %6, %7, " \
        " %8, %9, %10, %11, %12, %13, %14, %15, " \
        " %16, %17, %18, %19, %20, %21, %22, %23, " \
        " %24, %25, %26, %27, %28, %29, %30, %31}, [%32];" \
        : "=r"((r)[0]),  "=r"((r)[1]),  "=r"((r)[2]),  "=r"((r)[3]), \
          "=r"((r)[4]),  "=r"((r)[5]),  "=r"((r)[6]),  "=r"((r)[7]), \
          "=r"((r)[8]),  "=r"((r)[9]),  "=r"((r)[10]), "=r"((r)[11]), \
          "=r"((r)[12]), "=r"((r)[13]), "=r"((r)[14]), "=r"((r)[15]), \
          "=r"((r)[16]), "=r"((r)[17]), "=r"((r)[18]), "=r"((r)[19]), \
          "=r"((r)[20]), "=r"((r)[21]), "=r"((r)[22]), "=r"((r)[23]), \
          "=r"((r)[24]), "=r"((r)[25]), "=r"((r)[26]), "=r"((r)[27]), \
          "=r"((r)[28]), "=r"((r)[29]), "=r"((r)[30]), "=r"((r)[31]) \
        : "r"(addr))
#endif  // TC05

// ---------------- weight split: 2 elems/thread, row map r -> r*rowmul+rowadd ---
__global__ void wsplit_k(const float* __restrict__ src, __nv_bfloat16* __restrict__ hi,
                         __nv_bfloat16* __restrict__ lo, int layers, int Nr, int Nb,
                         int K, int Kp, int rowmul, int rowadd)
{
    int e = (blockIdx.x*blockDim.x + threadIdx.x) * 2;
    if (e >= layers*Nr*K) return;
    int k = e % K;
    int r = (e / K) % Nr;
    int l = e / (K*Nr);
    float2 v = *(const float2*)(src + e);
    __nv_bfloat16 h0 = __float2bfloat16_rn(v.x);
    __nv_bfloat16 l0 = __float2bfloat16_rn(v.x - __bfloat162float(h0));
    __nv_bfloat16 h1 = __float2bfloat16_rn(v.y);
    __nv_bfloat16 l1 = __float2bfloat16_rn(v.y - __bfloat162float(h1));
    size_t dst = ((size_t)l*Nb + (size_t)r*rowmul + rowadd)*Kp + k;
    *(__nv_bfloat162*)(hi + dst) = __nv_bfloat162(h0, h1);
    *(__nv_bfloat162*)(lo + dst) = __nv_bfloat162(l0, l1);
}

// ---------------- embedding ---------------------------------------------------
__global__ void embed_k(const int* __restrict__ x, const float* __restrict__ emb,
                        const float* __restrict__ pos, float* __restrict__ h)
{
    int t = blockIdx.x;
    int d = threadIdx.x;
    int tok = x[t];
    int l = t & (Lsz-1);
    h[(size_t)t*Dm + d] = emb[(size_t)tok*Dm + d] + pos[(size_t)l*Dm + d];
}

// ---------------- rmsnorm (warp per token), vectorized -------------------------
__global__ void rmsnorm_k(const float* __restrict__ x, const float* __restrict__ scale,
                          __nv_bfloat16* __restrict__ yh, __nv_bfloat16* __restrict__ yl)
{
    int gw   = (blockIdx.x*blockDim.x + threadIdx.x) >> 5;
    int lane = threadIdx.x & 31;
    if (gw >= TOK) return;
    const float* xr = x + (size_t)gw*Dm;
    const float4* x4 = (const float4*)xr;
    float4 va = x4[lane];
    float4 vb = x4[lane + 32];
    float  vc = xr[256 + lane];
    float ss = va.x*va.x + va.y*va.y + va.z*va.z + va.w*va.w
             + vb.x*vb.x + vb.y*vb.y + vb.z*vb.z + vb.w*vb.w
             + vc*vc;
#pragma unroll
    for (int off = 16; off; off >>= 1) ss += __shfl_xor_sync(~0u, ss, off);
    float norm = sqrtf(ss * (1.f/Dm));
    float inv  = 1.f / (norm + 1e-6f);

    const float4* s4 = (const float4*)scale;
    float4 sa = s4[lane];
    float4 sb = s4[lane + 32];
    float  sc = scale[256 + lane];

    size_t base = (size_t)gw*KP1;
    float y[8] = { sa.x*va.x*inv, sa.y*va.y*inv, sa.z*va.z*inv, sa.w*va.w*inv,
                   sb.x*vb.x*inv, sb.y*vb.y*inv, sb.z*vb.z*inv, sb.w*vb.w*inv };
    __nv_bfloat16 hh[8], ll[8];
#pragma unroll
    for (int j = 0; j < 8; j++) {
        hh[j] = __float2bfloat16_rn(y[j]);
        ll[j] = __float2bfloat16_rn(y[j] - __bfloat162float(hh[j]));
    }
    *(__nv_bfloat162*)(yh + base + 4*lane)       = __nv_bfloat162(hh[0], hh[1]);
    *(__nv_bfloat162*)(yh + base + 4*lane + 2)   = __nv_bfloat162(hh[2], hh[3]);
    *(__nv_bfloat162*)(yh + base + 128 + 4*lane)     = __nv_bfloat162(hh[4], hh[5]);
    *(__nv_bfloat162*)(yh + base + 128 + 4*lane + 2) = __nv_bfloat162(hh[6], hh[7]);
    *(__nv_bfloat162*)(yl + base + 4*lane)       = __nv_bfloat162(ll[0], ll[1]);
    *(__nv_bfloat162*)(yl + base + 4*lane + 2)   = __nv_bfloat162(ll[2], ll[3]);
    *(__nv_bfloat162*)(yl + base + 128 + 4*lane)     = __nv_bfloat162(ll[4], ll[5]);
    *(__nv_bfloat162*)(yl + base + 128 + 4*lane + 2) = __nv_bfloat162(ll[6], ll[7]);
    float yc = sc*vc*inv;
    bf16split(yc, yh + base + 256 + lane, yl + base + 256 + lane);
}

// ---------------- tcgen05 bf16x3 GEMM (M128 x N96 tile, 2 CTAs/SM) ------------
// mode 0: C = A*B^T; 1: +R; 2: silu-fused bf16 out; 3: rec sigmoid transform.
#define STG_B 57344
#define GSMEM (2*STG_B)

__global__ void __launch_bounds__(256) gemm5_k(
    const __nv_bfloat16* __restrict__ Ah, const __nv_bfloat16* __restrict__ Al,
    const __nv_bfloat16* __restrict__ Bh, const __nv_bfloat16* __restrict__ Bl,
    const float* __restrict__ R, float* __restrict__ C,
    __nv_bfloat16* __restrict__ Oh, __nv_bfloat16* __restrict__ Ol,
    int Nreal, int K, int mode)
{
#if TC05
    extern __shared__ __align__(1024) char smraw[];
    __shared__ uint32_t s_tmem;
    __shared__ __align__(8) unsigned long long s_mbar[2];

    const int tid  = threadIdx.x;
    const int wid  = tid >> 5;
    const int lane = tid & 31;
    const int m0   = blockIdx.y * 128;
    const int n0   = blockIdx.x * 96;
    const int nch  = K >> 6;

    uint32_t smb = (uint32_t)__cvta_generic_to_shared(smraw);
    uint32_t mb0 = (uint32_t)__cvta_generic_to_shared(&s_mbar[0]);
    uint32_t mb1 = (uint32_t)__cvta_generic_to_shared(&s_mbar[1]);

    if (wid == 0) {
        asm volatile("tcgen05.alloc.cta_group::1.sync.aligned.shared::cta.b32 [%0], %1;"
            :: "r"((uint32_t)__cvta_generic_to_shared(&s_tmem)), "r"(128u) : "memory");
        asm volatile("tcgen05.relinquish_alloc_permit.cta_group::1.sync.aligned;");
    }
    if (tid == 0) {
        asm volatile("mbarrier.init.shared.b64 [%0], %1;" :: "r"(mb0), "r"(1u) : "memory");
        asm volatile("mbarrier.init.shared.b64 [%0], %1;" :: "r"(mb1), "r"(1u) : "memory");
    }
    __syncthreads();
    const uint32_t tmem = s_tmem;

    const char* gA0 = (const char*)(Ah + (size_t)m0*K);
    const char* gA1 = (const char*)(Al + (size_t)m0*K);
    const char* gB0 = (const char*)(Bh + (size_t)n0*K);
    const char* gB1 = (const char*)(Bl + (size_t)n0*K);
    const size_t pitch = (size_t)K * 2;

#define LOAD_CHUNK(c)                                                             \
    do {                                                                          \
        int st_ = (c) & 1;                                                        \
        char* sb_ = smraw + st_*STG_B;                                            \
        _Pragma("unroll")                                                         \
        for (int i_ = 0; i_ < 4; i_++) {                                          \
            int idx_ = i_*256 + tid;                                              \
            int row_ = idx_ >> 3;                                                 \
            int kq_  = (idx_ & 7) << 4;                                           \
            int so_  = row_*128 + kq_;  so_ ^= (so_ >> 3) & 0x70;                 \
            size_t go_ = (size_t)row_*pitch + (c)*128 + kq_;                      \
            unsigned int d0_ = (unsigned int)__cvta_generic_to_shared(sb_ + so_); \
            asm volatile("cp.async.cg.shared.global [%0], [%1], 16;"              \
                         :: "r"(d0_), "l"(gA0 + go_));                            \
            unsigned int d1_ = (unsigned int)__cvta_generic_to_shared(sb_ + 16384 + so_); \
            asm volatile("cp.async.cg.shared.global [%0], [%1], 16;"              \
                         :: "r"(d1_), "l"(gA1 + go_));                            \
        }                                                                         \
        _Pragma("unroll")                                                         \
        for (int i_ = 0; i_ < 3; i_++) {                                          \
            int idx_ = i_*256 + tid;                                              \
            int row_ = idx_ >> 3;                                                 \
            int kq_  = (idx_ & 7) << 4;                                           \
            int so_  = row_*128 + kq_;  so_ ^= (so_ >> 3) & 0x70;                 \
            size_t go_ = (size_t)row_*pitch + (c)*128 + kq_;                      \
            unsigned int d2_ = (unsigned int)__cvta_generic_to_shared(sb_ + 32768 + so_); \
            asm volatile("cp.async.cg.shared.global [%0], [%1], 16;"              \
                         :: "r"(d2_), "l"(gB0 + go_));                            \
            unsigned int d3_ = (unsigned int)__cvta_generic_to_shared(sb_ + 45056 + so_); \
            asm volatile("cp.async.cg.shared.global [%0], [%1], 16;"              \
                         :: "r"(d3_), "l"(gB1 + go_));                            \
        }                                                                         \
        asm volatile("cp.async.commit_group;");                                   \
    } while (0)

    LOAD_CHUNK(0);
    if (nch > 1) LOAD_CHUNK(1);

    int ph0 = 0, ph1 = 0;
    const uint32_t idesc = 0x8180490u;   // F32 acc, BF16xBF16, N=96, M=128

    for (int c = 0; c < nch; c++) {
        int st = c & 1;
        if (c + 1 < nch) asm volatile("cp.async.wait_group 1;" ::: "memory");
        else             asm volatile("cp.async.wait_group 0;" ::: "memory");
        asm volatile("fence.proxy.async.shared::cta;" ::: "memory");
        __syncthreads();

        if (wid == 0 && elect1()) {
            uint32_t b = smb + st*STG_B;
            uint64_t dAh = mk_desc(b);
            uint64_t dAl = mk_desc(b + 16384);
            uint64_t dBh = mk_desc(b + 32768);
            uint64_t dBl = mk_desc(b + 45056);
            uint64_t ads[3] = {dAh, dAh, dAl};
            uint64_t bds[3] = {dBh, dBl, dBh};
#pragma unroll
            for (int t = 0; t < 3; t++)
#pragma unroll
                for (int k = 0; k < 4; k++)
                    mma_f16_ss(tmem, ads[t] + 2*k, bds[t] + 2*k, idesc,
                               !(c == 0 && t == 0 && k == 0));
            uint32_t mb = st ? mb1 : mb0;
            asm volatile("tcgen05.commit.cta_group::1.mbarrier::arrive::one.shared::cluster.b64 [%0];"
                         :: "r"(mb) : "memory");
        }

        if (c + 2 < nch) {
            if (st) { mbar_wait(mb1, ph1); ph1 ^= 1; }
            else    { mbar_wait(mb0, ph0); ph0 ^= 1; }
            LOAD_CHUNK(c + 2);
        }
    }
    for (int c = (nch >= 2 ? nch - 2 : 0); c < nch; c++) {
        int st = c & 1;
        if (st) { mbar_wait(mb1, ph1); ph1 ^= 1; } else { mbar_wait(mb0, ph0); ph0 ^= 1; }
    }
    asm volatile("tcgen05.fence::after_thread_sync;" ::: "memory");
    __syncthreads();

    float* smf = (float*)smraw;
    if (wid < 4) {
        int row = wid*32 + lane;
#pragma unroll
        for (int cb = 0; cb < 3; cb++) {
            uint32_t r[32];
            LDTM32(r, tmem + cb*32);
            asm volatile("tcgen05.wait::ld.sync.aligned;" ::: "memory");
            float* srow = smf + row*97 + cb*32;
#pragma unroll
            for (int q = 0; q < 32; q++) srow[q] = __uint_as_float(r[q]);
        }
    }
    asm volatile("tcgen05.fence::before_thread_sync;" ::: "memory");
    __syncthreads();

    if (mode == 2) {
        int p0 = n0 >> 1;
#pragma unroll
        for (int i = 0; i < 24; i++) {
            int idx = i*256 + tid;
            int row = idx / 48;
            int j   = idx % 48;
            int p = p0 + j;
            if (p < D3) {
                const float* s = smf + row*97 + 2*j;
                float g = s[0], u = s[1];
                float v = (g / (1.f + __expf(-g))) * u;
                size_t o = (size_t)(m0 + row)*KP3 + p;
                bf16split(v, Oh + o, Ol + o);
            }
        }
    } else {
        int region = (mode == 3) ? ((n0 < Dm) ? 0 : (n0 < 2*Dm) ? 1 : 2) : 1;
#pragma unroll
        for (int i = 0; i < 12; i++) {
            int idx = i*256 + tid;
            int row = idx / 24;
            int c4  = (idx % 24) << 2;
            int n = n0 + c4;
            if (n < Nreal) {
                const float* s = smf + row*97 + c4;
                float4 v = make_float4(s[0], s[1], s[2], s[3]);
                size_t off = (size_t)(m0 + row)*Nreal + n;
                if (mode == 1) {
                    float4 rr = *(const float4*)(R + off);
                    v.x += rr.x; v.y += rr.y; v.z += rr.z; v.w += rr.w;
                } else if (mode == 3) {
                    if (region == 0) {
                        v.x = 1.f/(1.f + __expf(-v.x)); v.y = 1.f/(1.f + __expf(-v.y));
                        v.z = 1.f/(1.f + __expf(-v.z)); v.w = 1.f/(1.f + __expf(-v.w));
                    } else if (region == 2) {
                        v.x = 1.f/(1.f + __expf(1.f - v.x)); v.y = 1.f/(1.f + __expf(1.f - v.y));
                        v.z = 1.f/(1.f + __expf(1.f - v.z)); v.w = 1.f/(1.f + __expf(1.f - v.w));
                    }
                }
                *(float4*)(C + off) = v;
            }
        }
    }

    __syncthreads();
    if (tid == 0) {
        asm volatile("mbarrier.inval.shared.b64 [%0];" :: "r"(mb0) : "memory");
        asm volatile("mbarrier.inval.shared.b64 [%0];" :: "r"(mb1) : "memory");
    }
    if (wid == 0)
        asm volatile("tcgen05.dealloc.cta_group::1.sync.aligned.b32 %0, %1;" :: "r"(tmem), "r"(128u));
#undef LOAD_CHUNK
#endif  // TC05
}

// ---------------- attention: 64 q/CTA, all K/V staged once (float4 loads) ------
// Heaviest query groups launched first for better wave packing.
__global__ void __launch_bounds__(512) attn_k(
    const float* __restrict__ qkv,
    __nv_bfloat16* __restrict__ oh, __nv_bfloat16* __restrict__ ol)
{
    extern __shared__ float asm_[];
    float (*sK)[37] = (float(*)[37])asm_;
    float (*sV)[37] = (float(*)[37])(asm_ + 512*37);

    int tid  = threadIdx.x;
    int wid  = tid >> 5;
    int lane = tid & 31;
    int bh = blockIdx.x >> 3;
    int qg = 7 - (blockIdx.x & 7);      // largest groups first
    int b = bh >> 3, h = bh & 7;

    int rows = (qg + 1) * 64;
    const float* kvbase = qkv + (size_t)b*Lsz*D3 + Dm + h*HD;

    // float4 staging: 9 float4 per row (HD=36), row starts 16B-aligned
    for (int idx = tid; idx < rows*9; idx += 512) {
        int kk = idx / 9;
        int j4 = idx % 9;
        const float* src = kvbase + (size_t)kk*D3 + j4*4;
        float4 kv = *(const float4*)src;
        float4 vv = *(const float4*)(src + Dm);
        float* kd = &sK[kk][j4*4];
        kd[0] = kv.x; kd[1] = kv.y; kd[2] = kv.z; kd[3] = kv.w;
        float* vd = &sV[kk][j4*4];
        vd[0] = vv.x; vd[1] = vv.y; vd[2] = vv.z; vd[3] = vv.w;
    }
    __syncthreads();

#pragma unroll
    for (int t = 0; t < 4; t++) {
        int q = qg*64 + t*16 + wid;

        const float* qrow = qkv + (size_t)(b*Lsz + q)*D3 + h*HD;
        float qv[HD];
#pragma unroll
        for (int d = 0; d < HD; d++) qv[d] = qrow[d] * (1.f/6.f);

        float m = -1e30f, ssum = 0.f;
        float o[HD];
#pragma unroll
        for (int d = 0; d < HD; d++) o[d] = 0.f;

        int nkc = (q >> 7) + 1;
        for (int kc = 0; kc < nkc; kc++) {
            float s[4], p[4];
            float cm = -1e30f;
#pragma unroll
            for (int j = 0; j < 4; j++) {
                int kk = (kc << 7) + lane + 32*j;
                s[j] = -1e30f;
                if (kk <= q) {
                    float a = 0.f;
#pragma unroll
                    for (int d = 0; d < HD; d++) a += qv[d] * sK[kk][d];
                    s[j] = a;
                }
                cm = fmaxf(cm, s[j]);
            }
#pragma unroll
            for (int off = 16; off; off >>= 1) cm = fmaxf(cm, __shfl_xor_sync(~0u, cm, off));
            float nm = fmaxf(m, cm);
            float alpha = __expf(m - nm);
            float ps = 0.f;
#pragma unroll
            for (int j = 0; j < 4; j++) {
                int kk = (kc << 7) + lane + 32*j;
                p[j] = (kk <= q) ? __expf(s[j] - nm) : 0.f;
                ps += p[j];
            }
#pragma unroll
            for (int off = 16; off; off >>= 1) ps += __shfl_xor_sync(~0u, ps, off);
            ssum = ssum*alpha + ps;
#pragma unroll
            for (int d = 0; d < HD; d++) {
                float acc = o[d]*alpha;
#pragma unroll
                for (int j = 0; j < 4; j++) {
                    int kk = (kc << 7) + lane + 32*j;
                    acc += p[j]*sV[kk][d];
                }
                o[d] = acc;
            }
            m = nm;
        }
#pragma unroll
        for (int d = 0; d < HD; d++) {
#pragma unroll
            for (int off = 16; off; off >>= 1) o[d] += __shfl_xor_sync(~0u, o[d], off);
        }
        if (lane == 0) {
            float inv = 1.f/ssum;
            size_t base = (size_t)(b*Lsz + q)*KP1 + h*HD;
#pragma unroll
            for (int d = 0; d < HD; d++)
                bf16split(o[d]*inv, oh + base + d, ol + base + d);
        }
    }
}

// ---------------- parallel linear recurrence scan (2 passes) -------------------
__global__ void scan1_k(const float* __restrict__ gvf,
                        float* __restrict__ ca, float* __restrict__ ch)
{
    int idx = blockIdx.x*blockDim.x + threadIdx.x;
    if (idx >= Bsz*NCHS*Dm) return;
    int d = idx % Dm;
    int c = (idx / Dm) % NCHS;
    int b = idx / (Dm*NCHS);
    const float* base = gvf + ((size_t)b*Lsz + c*CHL)*D3;
    float a = 1.f, h = 0.f;
    for (int l = 0; l < CHL; l++) {
        const float* r = base + (size_t)l*D3;
        float v = r[Dm + d], ft = r[2*Dm + d];
        h = ft*h + (1.f - ft)*v;
        a *= ft;
    }
    ca[idx] = a;
    ch[idx] = h;
}

// scan3: reconstruct carry-in from chunk summaries (same FMA order as old scan2),
// then replay the chunk and write g*h.
__global__ void scan3_k(const float* __restrict__ gvf,
                        const float* __restrict__ ca, const float* __restrict__ ch,
                        __nv_bfloat16* __restrict__ oh, __nv_bfloat16* __restrict__ ol)
{
    int idx = blockIdx.x*blockDim.x + threadIdx.x;
    if (idx >= Bsz*NCHS*Dm) return;
    int d = idx % Dm;
    int c = (idx / Dm) % NCHS;
    int b = idx / (Dm*NCHS);

    float h = 0.f;
    for (int cc = 0; cc < c; cc++) {
        size_t o = ((size_t)b*NCHS + cc)*Dm + d;
        h = ca[o]*h + ch[o];
    }

    const float* base = gvf + ((size_t)b*Lsz + c*CHL)*D3;
    for (int l = 0; l < CHL; l++) {
        const float* r = base + (size_t)l*D3;
        float gs = r[d], v = r[Dm + d], ft = r[2*Dm + d];
        h = ft*h + (1.f - ft)*v;
        size_t o = ((size_t)(b*Lsz + c*CHL + l))*KP1 + d;
        bf16split(gs*h, oh + o, ol + o);
    }
}

// ---------------- host orchestration -------------------------------------------
static inline void run_gemm(const __nv_bfloat16* Ah, const __nv_bfloat16* Al,
                            const __nv_bfloat16* wh, const __nv_bfloat16* wl, size_t woff,
                            const float* R, float* C,
                            __nv_bfloat16* Oh, __nv_bfloat16* Ol,
                            int Nb, int Nreal, int Kp, int mode)
{
    dim3 grid(Nb/96, TOK/128);
    gemm5_k<<<grid, 256, GSMEM>>>(Ah, Al, wh + woff, wl + woff, R, C, Oh, Ol, Nreal, Kp, mode);
}

extern "C" void kernel_launch(void* const* d_in, const int* in_sizes, int n_in,
                              void* d_out, int out_size)
{
    const int*   x         = (const int*)  d_in[0];
    const float* emb       = (const float*)d_in[1];
    const float* pos_emb   = (const float*)d_in[2];
    const float* attn_qkv  = (const float*)d_in[3];
    const float* attn_out  = (const float*)d_in[4];
    const float* attn_norm = (const float*)d_in[5];
    const float* rec_in    = (const float*)d_in[6];
    const float* rec_out   = (const float*)d_in[7];
    const float* rec_norm  = (const float*)d_in[8];
    const float* ffn_gate  = (const float*)d_in[9];
    const float* ffn_up    = (const float*)d_in[10];
    const float* ffn_down  = (const float*)d_in[11];
    const float* ffn_norm  = (const float*)d_in[12];
    const float* final_nrm = (const float*)d_in[13];
    float* out = (float*)d_out;

    static int smem_set = 0;
    if (!smem_set) {
        cudaFuncSetAttribute(gemm5_k, cudaFuncAttributeMaxDynamicSharedMemorySize, GSMEM);
        cudaFuncSetAttribute(attn_k,  cudaFuncAttributeMaxDynamicSharedMemorySize, ASMEM);
        smem_set = 1;
    }

    float *ph, *pa, *pca, *pch;
    __nv_bfloat16 *pwh, *pwl, *pxnh, *pxnl, *pash, *pasl, *pth, *ptl;
    cudaGetSymbolAddress((void**)&ph,  g_h);
    cudaGetSymbolAddress((void**)&pa,  g_a);
    cudaGetSymbolAddress((void**)&pca, g_ca);
    cudaGetSymbolAddress((void**)&pch, g_ch);
    cudaGetSymbolAddress((void**)&pwh, g_wh);
    cudaGetSymbolAddress((void**)&pwl, g_wl);
    cudaGetSymbolAddress((void**)&pxnh, g_xnh);
    cudaGetSymbolAddress((void**)&pxnl, g_xnl);
    cudaGetSymbolAddress((void**)&pash, g_ash);
    cudaGetSymbolAddress((void**)&pasl, g_asl);
    cudaGetSymbolAddress((void**)&pth, g_th);
    cudaGetSymbolAddress((void**)&ptl, g_tl);

    struct { const float* src; size_t off; int layers, Nr, Nb, K, Kp, rowmul, rowadd; } ws[8] = {
        {attn_qkv, WQKV,   4, 864, 864, 288, 320, 1, 0},
        {attn_out, WAOUT,  4, 288, 288, 288, 320, 1, 0},
        {rec_in,   WRIN,  10, 864, 864, 288, 320, 1, 0},
        {rec_out,  WROUT, 10, 288, 288, 288, 320, 1, 0},
        {ffn_gate, WGU,   14, 864, GUN, 288, 320, 2, 0},
        {ffn_up,   WGU,   14, 864, GUN, 288, 320, 2, 1},
        {ffn_down, WDOWN, 14, 288, 288, 864, 896, 1, 0},
        {emb,      WEMB,   1, 4096, VP, 288, 320, 1, 0},
    };
    for (int i = 0; i < 8; i++) {
        int tot = ws[i].layers * ws[i].Nr * ws[i].K;
        wsplit_k<<<(tot/2 + 255)/256, 256>>>(ws[i].src, pwh + ws[i].off, pwl + ws[i].off,
                                             ws[i].layers, ws[i].Nr, ws[i].Nb, ws[i].K,
                                             ws[i].Kp, ws[i].rowmul, ws[i].rowadd);
    }

    const int rms_blocks  = (TOK*32 + 255)/256;
    const int sc13_blocks = (Bsz*NCHS*Dm + 255)/256;

    embed_k<<<TOK, Dm>>>(x, emb, pos_emb, ph);

    int ai = 0, ri = 0;
    for (int i = 0; i < 14; i++) {
        bool is_attn = ((i + 1) % 3 == 0);
        if (is_attn) {
            rmsnorm_k<<<rms_blocks, 256>>>(ph, attn_norm + (size_t)ai*Dm, pxnh, pxnl);
            run_gemm(pxnh, pxnl, pwh, pwl, WQKV + (size_t)ai*864*320, nullptr, pa,
                     nullptr, nullptr, 864, D3, 320, 0);
            attn_k<<<Bsz*Hh*8, 512, ASMEM>>>(pa, pth, ptl);
            run_gemm(pth, ptl, pwh, pwl, WAOUT + (size_t)ai*288*320, ph, ph,
                     nullptr, nullptr, 288, Dm, 320, 1);
            ai++;
        } else {
            rmsnorm_k<<<rms_blocks, 256>>>(ph, rec_norm + (size_t)ri*Dm, pxnh, pxnl);
            run_gemm(pxnh, pxnl, pwh, pwl, WRIN + (size_t)ri*864*320, nullptr, pa,
                     nullptr, nullptr, 864, D3, 320, 3);
            scan1_k<<<sc13_blocks, 256>>>(pa, pca, pch);
            scan3_k<<<sc13_blocks, 256>>>(pa, pca, pch, pth, ptl);
            run_gemm(pth, ptl, pwh, pwl, WROUT + (size_t)ri*288*320, ph, ph,
                     nullptr, nullptr, 288, Dm, 320, 1);
            ri++;
        }
        rmsnorm_k<<<rms_blocks, 256>>>(ph, ffn_norm + (size_t)i*Dm, pxnh, pxnl);
        run_gemm(pxnh, pxnl, pwh, pwl, WGU + (size_t)i*GUN*320, nullptr, nullptr,
                 pash, pasl, GUN, GUN, 320, 2);
        run_gemm(pash, pasl, pwh, pwl, WDOWN + (size_t)i*288*896, ph, ph,
                 nullptr, nullptr, 288, Dm, 896, 1);
    }

    rmsnorm_k<<<rms_blocks, 256>>>(ph, final_nrm, pxnh, pxnl);
    run_gemm(pxnh, pxnl, pwh, pwl, WEMB, nullptr, out, nullptr, nullptr, VP, Vv, 320, 0);
}